// round 11
// baseline (speedup 1.0000x reference)
#include <cuda_runtime.h>

#define NS 10
#define ND 32
#define NL 4
#define NB 1024
#define BPT 2

typedef unsigned long long u64;

// Low half (rows h=0..15, v=0..511) of each layer's 32x32 dend_w matrix,
// padded: cdw[l*512 + 0] = 0 (empty subset), cdw[l*512 + v] = dend_w[l][v-1].
// Zero-initialized at module load; the per-launch memcpys only write v>=1.
__constant__ float cdw[NL * 512];

// ---- packed f32x2 helpers (sm_103a) ----
__device__ __forceinline__ u64 ffma2(u64 a, u64 b, u64 c) {
    u64 d;
    asm("fma.rn.f32x2 %0, %1, %2, %3;" : "=l"(d) : "l"(a), "l"(b), "l"(c));
    return d;
}
__device__ __forceinline__ u64 fadd2(u64 a, u64 b) {
    u64 d;
    asm("add.rn.f32x2 %0, %1, %2;" : "=l"(d) : "l"(a), "l"(b));
    return d;
}
__device__ __forceinline__ u64 pack2(float lo, float hi) {
    u64 d;
    asm("mov.b64 %0, {%1, %2};" : "=l"(d) : "f"(lo), "f"(hi));
    return d;
}
__device__ __forceinline__ float hsum2(u64 v) {
    float lo, hi;
    asm("mov.b64 {%0, %1}, %2;" : "=f"(lo), "=f"(hi) : "l"(v));
    return lo + hi;
}
__device__ __forceinline__ void unpack2(u64 v, float& lo, float& hi) {
    asm("mov.b64 {%0, %1}, %2;" : "=f"(lo), "=f"(hi) : "l"(v));
}

__global__ __launch_bounds__(128, 4)
void dendrite_kernel(const float* __restrict__ x,
                     const float* __restrict__ k,
                     const float* __restrict__ w,
                     const float* __restrict__ q,
                     const float* __restrict__ dend_w,
                     const float* __restrict__ dend_b,
                     const float* __restrict__ lin_w,
                     const float* __restrict__ lin_b,
                     const float* __restrict__ final_w,
                     const float* __restrict__ final_b,
                     const float* __restrict__ ks,
                     float* __restrict__ out)
{
    // High half (rows h=16..31, v=512..1023): sdw[l*512 + j] = dend_w[l][511+j].
    __shared__ __align__(16) float sdw[NL * 512];
    __shared__ float sred[BPT][NL];

    const int tid = threadIdx.x;
    const int l   = tid >> 5;        // warp == layer
    const int d   = tid & 31;        // lane == dendrite
    const int b0  = blockIdx.x * BPT;

    #pragma unroll
    for (int it = 0; it < 16; ++it) {
        int i  = tid + it * 128;     // 0..2047
        int ll = i >> 9, j = i & 511;
        sdw[i] = dend_w[ll * 1023 + 511 + j];
    }

    // ---- setup: s_i = sigmoid(k*(w*x - q)) for both batch elements ----
    const int base = (l * ND + d) * NS;
    float sA[NS], sB[NS];
    #pragma unroll
    for (int i = 0; i < NS; ++i) {
        const float ki = k[base + i], wi = w[base + i], qi = q[base + i];
        float zA = ki * (wi * x[b0 * NS + i] - qi);
        float zB = ki * (wi * x[(b0 + 1) * NS + i] - qi);
        sA[i] = 1.0f / (1.0f + __expf(-zA));
        sB[i] = 1.0f / (1.0f + __expf(-zB));
    }

    // Subset products of low-5 mask bits (bit p of lo -> s[9-p]), per b
    u64 PpA[16], PpB[16];
    {
        float PloA[32], PloB[32];
        PloA[0] = 1.0f; PloB[0] = 1.0f;
        #pragma unroll
        for (int bit = 0; bit < 5; ++bit) {
            const float va = sA[9 - bit], vb = sB[9 - bit];
            #pragma unroll
            for (int u = 0; u < (1 << bit); ++u) {
                PloA[(1 << bit) + u] = PloA[u] * va;
                PloB[(1 << bit) + u] = PloB[u] * vb;
            }
        }
        #pragma unroll
        for (int u = 0; u < 16; ++u) {
            PpA[u] = pack2(PloA[2 * u], PloA[2 * u + 1]);
            PpB[u] = pack2(PloB[2 * u], PloB[2 * u + 1]);
        }
    }

    // h-tree factors: bit p (p=0..3) of h -> s[4-p]; h-bit4 -> s[0]
    u64 sHp[4];
    #pragma unroll
    for (int p = 0; p < 4; ++p) sHp[p] = pack2(sA[4 - p], sB[4 - p]);
    const u64 s0p = pack2(sA[0], sB[0]);

    __syncthreads();

    // ---- mainloop: two interleaved streams (const port + smem port).
    // Each 32-float h-row spans 8 ulonglong2 (j = 0..7), consuming Pp[0..15].
    const ulonglong2* __restrict__ crow =
        reinterpret_cast<const ulonglong2*>(cdw + (l << 9));
    const ulonglong2* __restrict__ srow =
        reinterpret_cast<const ulonglong2*>(sdw + (l << 9));

    u64 lvlC[4], lvlS[4];
    u64 resC = 0ULL, resS = 0ULL;

    #pragma unroll
    for (int h = 0; h < 16; ++h) {
        u64 tC0a = 0ULL, tC1a = 0ULL, tC0b = 0ULL, tC1b = 0ULL;
        u64 tS0a = 0ULL, tS1a = 0ULL, tS0b = 0ULL, tS1b = 0ULL;

        #pragma unroll
        for (int j = 0; j < 8; ++j) {
            ulonglong2 cv = crow[h * 8 + j];
            ulonglong2 sv = srow[h * 8 + j];
            tC0a = ffma2(cv.x, PpA[2 * j],     tC0a);
            tC1a = ffma2(cv.y, PpA[2 * j + 1], tC1a);
            tC0b = ffma2(cv.x, PpB[2 * j],     tC0b);
            tC1b = ffma2(cv.y, PpB[2 * j + 1], tC1b);
            tS0a = ffma2(sv.x, PpA[2 * j],     tS0a);
            tS1a = ffma2(sv.y, PpA[2 * j + 1], tS1a);
            tS0b = ffma2(sv.x, PpB[2 * j],     tS0b);
            tS1b = ffma2(sv.y, PpB[2 * j + 1], tS1b);
        }

        // g_h per stream, packed (A,B)
        u64 gC = pack2(hsum2(fadd2(tC0a, tC1a)), hsum2(fadd2(tC0b, tC1b)));
        u64 gS = pack2(hsum2(fadd2(tS0a, tS1a)), hsum2(fadd2(tS0b, tS1b)));

        // streaming binary-counter Horner trees (4 levels each)
        bool doneC = false, doneS = false;
        #pragma unroll
        for (int p = 0; p < 4; ++p) {
            if (!doneC) {
                if ((h >> p) & 1) gC = ffma2(gC, sHp[p], lvlC[p]);
                else { lvlC[p] = gC; doneC = true; }
            }
            if (!doneS) {
                if ((h >> p) & 1) gS = ffma2(gS, sHp[p], lvlS[p]);
                else { lvlS[p] = gS; doneS = true; }
            }
        }
        if (h == 15) { resC = gC; resS = gS; }
    }

    // combine halves: rows h>=16 carry the extra s[0] factor
    u64 res2 = ffma2(resS, s0p, resC);
    float resA, resB;
    unpack2(res2, resA, resB);

    // ---- epilogue: Linear(D,1) warp reduce, Linear(L,1), sigmoid ----
    const float lw = lin_w[l * ND + d];
    const float db = dend_b[l];
    float vA = (resA + db) * lw;
    float vB = (resB + db) * lw;
    #pragma unroll
    for (int off = 16; off; off >>= 1) {
        vA += __shfl_xor_sync(0xffffffffu, vA, off);
        vB += __shfl_xor_sync(0xffffffffu, vB, off);
    }
    if (d == 0) {
        const float fw = final_w[l], lb = lin_b[l];
        sred[0][l] = (vA + lb) * fw;
        sred[1][l] = (vB + lb) * fw;
    }
    __syncthreads();
    if (tid < BPT) {
        float fin = sred[tid][0] + sred[tid][1] + sred[tid][2] + sred[tid][3] + final_b[0];
        out[b0 + tid] = 1.0f / (1.0f + __expf(-ks[0] * fin));
    }
}

extern "C" void kernel_launch(void* const* d_in, const int* in_sizes, int n_in,
                              void* d_out, int out_size) {
    const float* x       = (const float*)d_in[0];
    const float* k       = (const float*)d_in[1];
    const float* w       = (const float*)d_in[2];
    const float* q       = (const float*)d_in[3];
    const float* dend_w  = (const float*)d_in[4];
    const float* dend_b  = (const float*)d_in[5];
    const float* lin_w   = (const float*)d_in[6];
    const float* lin_b   = (const float*)d_in[7];
    const float* final_w = (const float*)d_in[8];
    const float* final_b = (const float*)d_in[9];
    const float* ks      = (const float*)d_in[10];
    float* out = (float*)d_out;

    // Refresh the low half of each layer's matrix into constant memory.
    // D2D async copies: graph-capturable, no allocation. Slot v=0 of each
    // layer stays at its static-init value 0 (never written).
    for (int l = 0; l < NL; ++l) {
        cudaMemcpyToSymbolAsync(cdw, dend_w + l * 1023,
                                511 * sizeof(float),
                                (l * 512 + 1) * sizeof(float),
                                cudaMemcpyDeviceToDevice, 0);
    }

    dendrite_kernel<<<NB / BPT, 128>>>(x, k, w, q, dend_w, dend_b,
                                       lin_w, lin_b, final_w, final_b, ks, out);
}

// round 13
// speedup vs baseline: 1.5057x; 1.5057x over previous
#include <cuda_runtime.h>
#include <cuda_bf16.h>

#define NS 10
#define ND 32
#define NL 4
#define NB 1024

typedef unsigned int u32;

// Prepacked B fragments: g_Bpk[l][nt][lane][term] = uint4(b0_kt0, b1_kt0, b0_kt1, b1_kt1)
// term 0 = bf16 hi, term 1 = bf16 residual (val - f32(hi)).
__device__ __align__(16) uint4 g_Bpk[NL][4][32][2];

// cvt.rn.bf16x2.f32 d, a, b : upper16 = cvt(a), lower16 = cvt(b)
__device__ __forceinline__ u32 cvt2(float lo, float hi) {
    u32 r;
    asm("cvt.rn.bf16x2.f32 %0, %1, %2;" : "=r"(r) : "f"(hi), "f"(lo));
    return r;
}
__device__ __forceinline__ float lo_f(u32 p) { return __uint_as_float(p << 16); }
__device__ __forceinline__ float hi_f(u32 p) { return __uint_as_float(p & 0xffff0000u); }

__device__ __forceinline__ void mma_bf16(float* c, const u32* a, u32 b0, u32 b1) {
    asm volatile("mma.sync.aligned.m16n8k16.row.col.f32.bf16.bf16.f32 "
                 "{%0,%1,%2,%3}, {%4,%5,%6,%7}, {%8,%9}, {%0,%1,%2,%3};"
                 : "+f"(c[0]), "+f"(c[1]), "+f"(c[2]), "+f"(c[3])
                 : "r"(a[0]), "r"(a[1]), "r"(a[2]), "r"(a[3]), "r"(b0), "r"(b1));
}

// ============================================================
// Prep: pack DW_l (32x32, dwpad[0]=0) into per-lane mma B fragments.
// B[n][k] = DW[h = 8*nt + g][lo = k + 16*kt];  b0 = (k=2tq, 2tq+1), b1 = (+8,+9).
// ============================================================
__global__ void prep_kernel(const float* __restrict__ dend_w) {
    int l    = blockIdx.x;
    int nt   = threadIdx.x >> 5;
    int lane = threadIdx.x & 31;
    int g = lane >> 2, tq = lane & 3;
    int h = nt * 8 + g;

    float v[8];
    #pragma unroll
    for (int kt = 0; kt < 2; ++kt)
        #pragma unroll
        for (int j = 0; j < 4; ++j) {
            int col = 2 * tq + (j & 1) + 8 * (j >> 1) + 16 * kt;
            int vv  = 32 * h + col;          // v index into padded dend_w
            v[kt * 4 + j] = vv ? dend_w[l * 1023 + vv - 1] : 0.0f;
        }
    u32 hi[4], lo[4];
    #pragma unroll
    for (int p = 0; p < 4; ++p) {
        hi[p] = cvt2(v[2 * p], v[2 * p + 1]);
        lo[p] = cvt2(v[2 * p] - lo_f(hi[p]), v[2 * p + 1] - hi_f(hi[p]));
    }
    g_Bpk[l][nt][lane][0] = make_uint4(hi[0], hi[1], hi[2], hi[3]);
    g_Bpk[l][nt][lane][1] = make_uint4(lo[0], lo[1], lo[2], lo[3]);
}

// ============================================================
// Main: block = 256 threads = 8 warps = (2 batch) x (4 layers).
// Warp: 32 rows (d = lane) of one (b, l). C[row, h] = Plo @ DW^T via mma,
// then dend = Phi-dot on C fragments, warp/block reduce, sigmoid.
// ============================================================
__global__ __launch_bounds__(256)
void main_kernel(const float* __restrict__ x,
                 const float* __restrict__ k,
                 const float* __restrict__ w,
                 const float* __restrict__ q,
                 const float* __restrict__ dend_b,
                 const float* __restrict__ lin_w,
                 const float* __restrict__ lin_b,
                 const float* __restrict__ final_w,
                 const float* __restrict__ final_b,
                 const float* __restrict__ ks,
                 float* __restrict__ out)
{
    // Per-warp A region: 32 rows x 144B (64B hi + 64B lo + 16B pad).
    __shared__ __align__(16) unsigned char sA[8 * 32 * 144];
    __shared__ float sfin[2][NL];

    const int tid  = threadIdx.x;
    const int wid  = tid >> 5, lane = tid & 31;
    const int l    = wid & 3,  bl   = wid >> 2;
    const int b    = blockIdx.x * 2 + bl;
    const int g    = lane >> 2, tq = lane & 3;

    // ---- s_i = sigmoid(k*(w*x - q)), row = (l, d=lane) ----
    const int base = (l * ND + lane) * NS;
    float s[NS];
    #pragma unroll
    for (int i = 0; i < NS; ++i) {
        float z = k[base + i] * (w[base + i] * x[b * NS + i] - q[base + i]);
        s[i] = 1.0f / (1.0f + __expf(-z));
    }

    // ---- Plo subset products (bit p of lo -> s[9-p]) ----
    float Plo[32];
    Plo[0] = 1.0f;
    #pragma unroll
    for (int bit = 0; bit < 5; ++bit) {
        const float sv = s[9 - bit];
        #pragma unroll
        for (int u = 0; u < (1 << bit); ++u)
            Plo[(1 << bit) + u] = Plo[u] * sv;
    }

    // ---- stage A row (bf16 hi + residual lo) into smem ----
    {
        uint4* rp = reinterpret_cast<uint4*>(sA + (wid * 32 + lane) * 144);
        u32 hi[16], lo[16];
        #pragma unroll
        for (int c = 0; c < 16; ++c)
            hi[c] = cvt2(Plo[2 * c], Plo[2 * c + 1]);
        #pragma unroll
        for (int c = 0; c < 16; ++c)
            lo[c] = cvt2(Plo[2 * c] - lo_f(hi[c]), Plo[2 * c + 1] - hi_f(hi[c]));
        rp[0] = make_uint4(hi[0],  hi[1],  hi[2],  hi[3]);
        rp[1] = make_uint4(hi[4],  hi[5],  hi[6],  hi[7]);
        rp[2] = make_uint4(hi[8],  hi[9],  hi[10], hi[11]);
        rp[3] = make_uint4(hi[12], hi[13], hi[14], hi[15]);
        rp[4] = make_uint4(lo[0],  lo[1],  lo[2],  lo[3]);
        rp[5] = make_uint4(lo[4],  lo[5],  lo[6],  lo[7]);
        rp[6] = make_uint4(lo[8],  lo[9],  lo[10], lo[11]);
        rp[7] = make_uint4(lo[12], lo[13], lo[14], lo[15]);
    }

    // ---- Phi factors for the 4 C-fragment rows (g, g+8, g+16, g+24) ----
    // h = 8*nt + 2*tq + e : bit0=e->s4, bits1-2=tq->s3,s2, bits3-4=nt->s1,s0
    float pb[4], s4m[4], cnt1[4], cnt2[4], cnt3[4];
    #pragma unroll
    for (int m = 0; m < 4; ++m) {
        int src = g + 8 * m;
        float a0 = __shfl_sync(0xffffffffu, s[0], src);
        float a1 = __shfl_sync(0xffffffffu, s[1], src);
        float a2 = __shfl_sync(0xffffffffu, s[2], src);
        float a3 = __shfl_sync(0xffffffffu, s[3], src);
        s4m[m]   = __shfl_sync(0xffffffffu, s[4], src);
        pb[m] = ((tq & 1) ? a3 : 1.0f) * ((tq & 2) ? a2 : 1.0f);
        cnt1[m] = a1; cnt2[m] = a0; cnt3[m] = a0 * a1;
    }
    __syncthreads();

    // ---- mma mainloop ----
    float dpart[4] = {0.0f, 0.0f, 0.0f, 0.0f};
    const u32* Aw = reinterpret_cast<const u32*>(sA + wid * 32 * 144);

    #pragma unroll
    for (int mt = 0; mt < 2; ++mt) {
        u32 Ah[2][4], Al[2][4];
        const int r0 = (16 * mt + g) * 36;       // row stride = 144B = 36 u32
        const int r1 = (16 * mt + g + 8) * 36;
        #pragma unroll
        for (int kt = 0; kt < 2; ++kt) {
            const int o = tq + 8 * kt;
            Ah[kt][0] = Aw[r0 + o];      Ah[kt][1] = Aw[r1 + o];
            Ah[kt][2] = Aw[r0 + o + 4];  Ah[kt][3] = Aw[r1 + o + 4];
            Al[kt][0] = Aw[r0 + o + 16]; Al[kt][1] = Aw[r1 + o + 16];
            Al[kt][2] = Aw[r0 + o + 20]; Al[kt][3] = Aw[r1 + o + 20];
        }
        #pragma unroll
        for (int nt = 0; nt < 4; ++nt) {
            uint4 BH = g_Bpk[l][nt][lane][0];
            uint4 BL = g_Bpk[l][nt][lane][1];
            float c[4] = {0.0f, 0.0f, 0.0f, 0.0f};
            mma_bf16(c, Ah[0], BH.x, BH.y);
            mma_bf16(c, Ah[1], BH.z, BH.w);
            mma_bf16(c, Ah[0], BL.x, BL.y);
            mma_bf16(c, Ah[1], BL.z, BL.w);
            mma_bf16(c, Al[0], BH.x, BH.y);
            mma_bf16(c, Al[1], BH.z, BH.w);

            const int m0 = 2 * mt, m1 = 2 * mt + 1;
            float f0 = (nt == 0) ? 1.0f : (nt == 1) ? cnt1[m0]
                     : (nt == 2) ? cnt2[m0] : cnt3[m0];
            float f1 = (nt == 0) ? 1.0f : (nt == 1) ? cnt1[m1]
                     : (nt == 2) ? cnt2[m1] : cnt3[m1];
            float p0 = pb[m0] * f0;
            float p1 = pb[m1] * f1;
            dpart[m0] += c[0] * p0 + c[1] * (p0 * s4m[m0]);
            dpart[m1] += c[2] * p1 + c[3] * (p1 * s4m[m1]);
        }
    }

    // ---- reduce: quad (h coverage), then lin_w dot across d-groups ----
    #pragma unroll
    for (int m = 0; m < 4; ++m) {
        dpart[m] += __shfl_xor_sync(0xffffffffu, dpart[m], 1);
        dpart[m] += __shfl_xor_sync(0xffffffffu, dpart[m], 2);
    }
    const float db = dend_b[l];
    float v = 0.0f;
    #pragma unroll
    for (int m = 0; m < 4; ++m)
        v = fmaf(dpart[m] + db, lin_w[l * ND + g + 8 * m], v);
    v += __shfl_xor_sync(0xffffffffu, v, 4);
    v += __shfl_xor_sync(0xffffffffu, v, 8);
    v += __shfl_xor_sync(0xffffffffu, v, 16);
    if (lane == 0) sfin[bl][l] = (v + lin_b[l]) * final_w[l];
    __syncthreads();

    if (tid < 2) {
        int bb = blockIdx.x * 2 + tid;
        float fin = sfin[tid][0] + sfin[tid][1] + sfin[tid][2] + sfin[tid][3]
                  + final_b[0];
        out[bb] = 1.0f / (1.0f + __expf(-ks[0] * fin));
    }
}

extern "C" void kernel_launch(void* const* d_in, const int* in_sizes, int n_in,
                              void* d_out, int out_size) {
    const float* x       = (const float*)d_in[0];
    const float* k       = (const float*)d_in[1];
    const float* w       = (const float*)d_in[2];
    const float* q       = (const float*)d_in[3];
    const float* dend_w  = (const float*)d_in[4];
    const float* dend_b  = (const float*)d_in[5];
    const float* lin_w   = (const float*)d_in[6];
    const float* lin_b   = (const float*)d_in[7];
    const float* final_w = (const float*)d_in[8];
    const float* final_b = (const float*)d_in[9];
    const float* ks      = (const float*)d_in[10];
    float* out = (float*)d_out;

    prep_kernel<<<NL, 128>>>(dend_w);
    main_kernel<<<NB / 2, 256>>>(x, k, w, q, dend_b,
                                 lin_w, lin_b, final_w, final_b, ks, out);
}